// round 7
// baseline (speedup 1.0000x reference)
#include <cuda_runtime.h>
#include <math.h>

#define BATCH 8
#define NPTS  2048
#define DIM   512
#define KNN   16
#define NROWS (BATCH*NPTS)

// ---------- scratch (static device globals; no runtime allocation) ----------
__device__ float g_fq[(size_t)NROWS*DIM];            // normalized ffq
__device__ float g_fp[(size_t)NROWS*DIM];            // normalized ffp
__device__ float g_w1[(size_t)NROWS*NPTS];           // similarity matrix (134 MB)
__device__ int   g_topk[(size_t)NROWS*KNN];

// =====================================================================
// Kernel 1: row L2-normalize ffq -> g_fq, ffp -> g_fp
// grid (NROWS, 2), block 256
// =====================================================================
__global__ void normalize_kernel(const float* __restrict__ ffq,
                                 const float* __restrict__ ffp) {
    int row = blockIdx.x;
    const float* src = (blockIdx.y == 0) ? ffq : ffp;
    float*       dst = (blockIdx.y == 0) ? g_fq : g_fp;
    const float* r = src + (size_t)row * DIM;
    int tid = threadIdx.x;

    float v0 = r[tid], v1 = r[tid + 256];
    __shared__ float red[256];
    red[tid] = v0 * v0 + v1 * v1;
    __syncthreads();
    #pragma unroll
    for (int s = 128; s > 0; s >>= 1) {
        if (tid < s) red[tid] += red[tid + s];
        __syncthreads();
    }
    float inv = 1.0f / (sqrtf(red[0]) + 1e-8f);
    float* d = dst + (size_t)row * DIM;
    d[tid]       = v0 * inv;
    d[tid + 256] = v1 * inv;
}

// =====================================================================
// Kernel 2: batched GEMM  w1[b,q,p] = dot(g_fq[b,q,:], g_fp[b,p,:])
// tile 64x64, BK=16, block 256 threads, 4x4 microtile
// grid (NPTS/64, NPTS/64, BATCH)
// =====================================================================
__global__ __launch_bounds__(256) void gemm_kernel() {
    const int b  = blockIdx.z;
    const float* Ab = g_fq + (size_t)b * NPTS * DIM;
    const float* Bb = g_fp + (size_t)b * NPTS * DIM;
    float*       Cb = g_w1 + (size_t)b * NPTS * NPTS;

    const int m0 = blockIdx.y * 64;
    const int n0 = blockIdx.x * 64;

    __shared__ float As[16][64];
    __shared__ float Bs[16][64];

    const int tid  = threadIdx.x;
    const int tx   = tid & 15;          // 0..15 -> n
    const int ty   = tid >> 4;          // 0..15 -> m
    const int lrow = tid >> 2;          // 0..63
    const int lk4  = (tid & 3) * 4;     // 0,4,8,12

    float acc[4][4];
    #pragma unroll
    for (int i = 0; i < 4; i++)
        #pragma unroll
        for (int j = 0; j < 4; j++) acc[i][j] = 0.f;

    for (int k0 = 0; k0 < DIM; k0 += 16) {
        float4 a4 = *(const float4*)(Ab + (size_t)(m0 + lrow) * DIM + k0 + lk4);
        float4 b4 = *(const float4*)(Bb + (size_t)(n0 + lrow) * DIM + k0 + lk4);
        As[lk4 + 0][lrow] = a4.x; As[lk4 + 1][lrow] = a4.y;
        As[lk4 + 2][lrow] = a4.z; As[lk4 + 3][lrow] = a4.w;
        Bs[lk4 + 0][lrow] = b4.x; Bs[lk4 + 1][lrow] = b4.y;
        Bs[lk4 + 2][lrow] = b4.z; Bs[lk4 + 3][lrow] = b4.w;
        __syncthreads();
        #pragma unroll
        for (int kk = 0; kk < 16; kk++) {
            float4 av = *(const float4*)&As[kk][ty * 4];
            float4 bv = *(const float4*)&Bs[kk][tx * 4];
            float a[4] = {av.x, av.y, av.z, av.w};
            float c[4] = {bv.x, bv.y, bv.z, bv.w};
            #pragma unroll
            for (int i = 0; i < 4; i++)
                #pragma unroll
                for (int j = 0; j < 4; j++)
                    acc[i][j] = fmaf(a[i], c[j], acc[i][j]);
        }
        __syncthreads();
    }
    #pragma unroll
    for (int i = 0; i < 4; i++) {
        float4 o = make_float4(acc[i][0], acc[i][1], acc[i][2], acc[i][3]);
        *(float4*)&Cb[(size_t)(m0 + ty * 4 + i) * NPTS + n0 + tx * 4] = o;
    }
}

// =====================================================================
// Kernel 3: exact top-16 per row of g_w1, matching jax.lax.top_k
// (descending values, ties broken by lower index). Iterative argmax.
// grid NROWS, block 256
// =====================================================================
__global__ void topk_kernel(float* __restrict__ outF) {
    const int row = blockIdx.x;
    const float* w = g_w1 + (size_t)row * NPTS;
    __shared__ float sv[NPTS];
    __shared__ float rv[8];
    __shared__ int   ri[8];
    const int tid = threadIdx.x;

    #pragma unroll
    for (int j = 0; j < 8; j++) sv[j * 256 + tid] = w[j * 256 + tid];
    __syncthreads();

    const size_t idx_base = (size_t)3 * NROWS * 3;   // after 3 float blocks

    for (int it = 0; it < KNN; it++) {
        float bv = -INFINITY; int bi = NPTS;
        #pragma unroll
        for (int j = 0; j < 8; j++) {
            int i = j * 256 + tid;          // ascending -> strict '>' keeps lowest idx
            float v = sv[i];
            if (v > bv) { bv = v; bi = i; }
        }
        // warp reduce with tie-break (lower index wins on equal value)
        #pragma unroll
        for (int o = 16; o > 0; o >>= 1) {
            float ov = __shfl_xor_sync(0xffffffffu, bv, o);
            int   oi = __shfl_xor_sync(0xffffffffu, bi, o);
            if (ov > bv || (ov == bv && oi < bi)) { bv = ov; bi = oi; }
        }
        if ((tid & 31) == 0) { rv[tid >> 5] = bv; ri[tid >> 5] = bi; }
        __syncthreads();
        if (tid == 0) {
            float fbv = rv[0]; int fbi = ri[0];
            #pragma unroll
            for (int wdx = 1; wdx < 8; wdx++) {
                if (rv[wdx] > fbv || (rv[wdx] == fbv && ri[wdx] < fbi)) {
                    fbv = rv[wdx]; fbi = ri[wdx];
                }
            }
            g_topk[(size_t)row * KNN + it] = fbi;
            outF[idx_base + (size_t)row * KNN + it] = (float)fbi;
            sv[fbi] = -INFINITY;
        }
        __syncthreads();
    }
}

// =====================================================================
// Kernel 4: gather + mean/max pool + refine linear + inv(R1),inv(R2)
//           + masked residual; writes q, q_refine (x2)
// grid NROWS, block 256
// =====================================================================
__device__ __forceinline__ void inv3_apply(const float* __restrict__ M,
                                           const float* v, float* out) {
    float a = M[0], b = M[1], c = M[2];
    float d = M[3], e = M[4], f = M[5];
    float g = M[6], h = M[7], i = M[8];
    float det = a * (e * i - f * h) - b * (d * i - f * g) + c * (d * h - e * g);
    float idet = 1.0f / det;
    float i00 = (e * i - f * h) * idet, i01 = (c * h - b * i) * idet, i02 = (b * f - c * e) * idet;
    float i10 = (f * g - d * i) * idet, i11 = (a * i - c * g) * idet, i12 = (c * d - a * f) * idet;
    float i20 = (d * h - e * g) * idet, i21 = (b * g - a * h) * idet, i22 = (a * e - b * d) * idet;
    out[0] = i00 * v[0] + i01 * v[1] + i02 * v[2];
    out[1] = i10 * v[0] + i11 * v[1] + i12 * v[2];
    out[2] = i20 * v[0] + i21 * v[1] + i22 * v[2];
}

__global__ void finalize_kernel(const float* __restrict__ q,
                                const float* __restrict__ ffp,
                                const float* __restrict__ ffq,
                                const float* __restrict__ R1,
                                const float* __restrict__ R2,
                                const int*   __restrict__ centroids,
                                const float* __restrict__ W,
                                const float* __restrict__ bias,
                                float* __restrict__ outF) {
    const int pt = blockIdx.x;                 // b*NPTS + n
    const int b  = pt / NPTS;
    const int tid = threadIdx.x;

    __shared__ int   sidx[KNN];
    __shared__ float s0[256], s1[256], s2[256];
    if (tid < KNN) sidx[tid] = g_topk[(size_t)pt * KNN + tid];
    __syncthreads();

    const float* fpB  = ffp + (size_t)b * NPTS * DIM;
    const float* qrow = ffq + (size_t)pt * DIM;

    float p0 = 0.f, p1 = 0.f, p2 = 0.f;
    #pragma unroll
    for (int half = 0; half < 2; half++) {
        int d = tid + half * 256;
        float s = 0.f, mx = -INFINITY;
        #pragma unroll
        for (int k = 0; k < KNN; k++) {
            float v = __ldg(&fpB[(size_t)sidx[k] * DIM + d]);
            s += v;
            mx = fmaxf(mx, v);
        }
        float avg = s * (1.0f / KNN);
        float qv  = qrow[d];
        p0 += qv * W[0 * 1536 + d] + avg * W[0 * 1536 + 512 + d] + mx * W[0 * 1536 + 1024 + d];
        p1 += qv * W[1 * 1536 + d] + avg * W[1 * 1536 + 512 + d] + mx * W[1 * 1536 + 1024 + d];
        p2 += qv * W[2 * 1536 + d] + avg * W[2 * 1536 + 512 + d] + mx * W[2 * 1536 + 1024 + d];
    }
    s0[tid] = p0; s1[tid] = p1; s2[tid] = p2;
    __syncthreads();
    #pragma unroll
    for (int s = 128; s > 0; s >>= 1) {
        if (tid < s) { s0[tid] += s0[tid + s]; s1[tid] += s1[tid + s]; s2[tid] += s2[tid + s]; }
        __syncthreads();
    }
    if (tid == 0) {
        float v[3] = { s0[0] + bias[0], s1[0] + bias[1], s2[0] + bias[2] };
        float t[3], r[3];
        inv3_apply(R1 + (size_t)pt * 9, v, t);
        inv3_apply(R2 + (size_t)pt * 9, t, r);
        float mask = (centroids[pt] >= NPTS) ? 1.0f : 0.0f;

        size_t base = (size_t)pt * 3;
        float q0 = q[base], q1 = q[base + 1], q2 = q[base + 2];
        // output 0: q passthrough
        outF[base] = q0; outF[base + 1] = q1; outF[base + 2] = q2;
        // outputs 1 & 2: q_refine
        float o0 = q0 + r[0] * mask;
        float o1 = q1 + r[1] * mask;
        float o2 = q2 + r[2] * mask;
        size_t off = (size_t)NROWS * 3;
        outF[off + base] = o0;  outF[off + base + 1] = o1;  outF[off + base + 2] = o2;
        outF[2 * off + base] = o0; outF[2 * off + base + 1] = o1; outF[2 * off + base + 2] = o2;
    }
}

// =====================================================================
extern "C" void kernel_launch(void* const* d_in, const int* in_sizes, int n_in,
                              void* d_out, int out_size) {
    const float* q         = (const float*)d_in[1];
    const float* ffp       = (const float*)d_in[2];
    const float* ffq       = (const float*)d_in[3];
    const float* R1        = (const float*)d_in[4];
    const float* R2        = (const float*)d_in[5];
    const int*   centroids = (const int*)  d_in[6];
    const float* W         = (const float*)d_in[7];
    const float* bias      = (const float*)d_in[8];
    float* outF = (float*)d_out;

    dim3 gN(NROWS, 2);
    normalize_kernel<<<gN, 256>>>(ffq, ffp);

    dim3 gG(NPTS / 64, NPTS / 64, BATCH);
    gemm_kernel<<<gG, 256>>>();

    topk_kernel<<<NROWS, 256>>>(outF);

    finalize_kernel<<<NROWS, 256>>>(q, ffp, ffq, R1, R2, centroids, W, bias, outF);
}

// round 11
// speedup vs baseline: 1.6629x; 1.6629x over previous
#include <cuda_runtime.h>
#include <cuda_bf16.h>
#include <math.h>
#include <stdint.h>

#define BATCH 8
#define NPTS  2048
#define DIM   512
#define KNN   16
#define NROWS (BATCH*NPTS)
#define NCAND 32

// ---------- scratch (static device globals; no runtime allocation) ----------
__device__ __align__(16) float         g_fq [(size_t)NROWS*DIM];   // normalized ffq (fp32)
__device__ __align__(16) float         g_fp [(size_t)NROWS*DIM];   // normalized ffp (fp32)
__device__ __align__(16) __nv_bfloat16 g_fqb[(size_t)NROWS*DIM];   // normalized ffq (bf16)
__device__ __align__(16) __nv_bfloat16 g_fpb[(size_t)NROWS*DIM];   // normalized ffp (bf16)
__device__ __align__(16) float         g_w1 [(size_t)NROWS*NPTS];  // bf16-mma similarity (fp32 acc)
__device__ int                         g_topk[(size_t)NROWS*KNN];

// =====================================================================
// Kernel 1: row L2-normalize (VERBATIM from the round-7 passing kernel
// so g_fq/g_fp bits are identical). grid (NROWS, 2), block 256
// =====================================================================
__global__ void normalize_kernel(const float* __restrict__ ffq,
                                 const float* __restrict__ ffp) {
    int row = blockIdx.x;
    const float* src = (blockIdx.y == 0) ? ffq : ffp;
    float*       dst = (blockIdx.y == 0) ? g_fq : g_fp;
    const float* r = src + (size_t)row * DIM;
    int tid = threadIdx.x;

    float v0 = r[tid], v1 = r[tid + 256];
    __shared__ float red[256];
    red[tid] = v0 * v0 + v1 * v1;
    __syncthreads();
    #pragma unroll
    for (int s = 128; s > 0; s >>= 1) {
        if (tid < s) red[tid] += red[tid + s];
        __syncthreads();
    }
    float inv = 1.0f / (sqrtf(red[0]) + 1e-8f);
    float* d = dst + (size_t)row * DIM;
    d[tid]       = v0 * inv;
    d[tid + 256] = v1 * inv;
}

// =====================================================================
// Kernel 1b: fp32 -> bf16 cast of the normalized features
// grid (NROWS, 2), block 256
// =====================================================================
__global__ void cast_bf16_kernel() {
    int row = blockIdx.x;
    const float*   src = (blockIdx.y == 0) ? g_fq : g_fp;
    __nv_bfloat16* dst = (blockIdx.y == 0) ? g_fqb : g_fpb;
    int tid = threadIdx.x;
    const float* s = src + (size_t)row * DIM;
    __nv_bfloat16* d = dst + (size_t)row * DIM;
    d[tid]       = __float2bfloat16(s[tid]);
    d[tid + 256] = __float2bfloat16(s[tid + 256]);
}

// =====================================================================
// Kernel 2: bf16 tensor-core GEMM  w1[b,q,p] = fq[b,q,:] . fp[b,p,:]
// CTA tile 128x128, BK=32, 8 warps (2x4), warp tile 64x32,
// mma.sync.m16n8k16, cp.async 2-stage pipeline, 80B-padded smem rows.
// grid (NPTS/128, NPTS/128, BATCH), block 256
// =====================================================================
#define BM 128
#define BN 128
#define SROW 40   // bf16 per smem row (32 data + 8 pad)

__device__ __forceinline__ void ldsm4(uint32_t& r0, uint32_t& r1,
                                      uint32_t& r2, uint32_t& r3, uint32_t addr) {
    asm volatile("ldmatrix.sync.aligned.m8n8.x4.shared.b16 {%0,%1,%2,%3}, [%4];"
                 : "=r"(r0), "=r"(r1), "=r"(r2), "=r"(r3) : "r"(addr));
}
__device__ __forceinline__ void mma16816(float& c0, float& c1, float& c2, float& c3,
                                         uint32_t a0, uint32_t a1, uint32_t a2, uint32_t a3,
                                         uint32_t b0, uint32_t b1) {
    asm volatile("mma.sync.aligned.m16n8k16.row.col.f32.bf16.bf16.f32 "
                 "{%0,%1,%2,%3}, {%4,%5,%6,%7}, {%8,%9}, {%0,%1,%2,%3};"
                 : "+f"(c0), "+f"(c1), "+f"(c2), "+f"(c3)
                 : "r"(a0), "r"(a1), "r"(a2), "r"(a3), "r"(b0), "r"(b1));
}
__device__ __forceinline__ void cpasync16(uint32_t saddr, const void* g) {
    asm volatile("cp.async.cg.shared.global [%0], [%1], 16;" :: "r"(saddr), "l"(g));
}

__global__ __launch_bounds__(256) void gemm_bf16_kernel() {
    __shared__ __align__(16) __nv_bfloat16 sA[2][BM * SROW];
    __shared__ __align__(16) __nv_bfloat16 sB[2][BN * SROW];

    const int b = blockIdx.z;
    const __nv_bfloat16* Ag = g_fqb + (size_t)b * NPTS * DIM;
    const __nv_bfloat16* Bg = g_fpb + (size_t)b * NPTS * DIM;
    float* Cb = g_w1 + (size_t)b * NPTS * NPTS;

    const int m0 = blockIdx.y * BM, n0 = blockIdx.x * BN;
    const int tid = threadIdx.x;
    const int lane = tid & 31, wid = tid >> 5;
    const int wm = wid >> 2, wn = wid & 3;    // warp grid 2(m) x 4(n)

    const int lrow = tid >> 1;
    const int lch  = (tid & 1) * 16;

    float acc[4][4][4];
    #pragma unroll
    for (int i = 0; i < 4; i++)
        #pragma unroll
        for (int j = 0; j < 4; j++)
            #pragma unroll
            for (int v = 0; v < 4; v++) acc[i][j][v] = 0.f;

    const uint32_t sA_base = (uint32_t)__cvta_generic_to_shared(&sA[0][0]);
    const uint32_t sB_base = (uint32_t)__cvta_generic_to_shared(&sB[0][0]);
    const uint32_t stageBytes = BM * SROW * 2;

    {
        uint32_t sa = sA_base + (uint32_t)(lrow * SROW + lch) * 2;
        const __nv_bfloat16* ga = Ag + (size_t)(m0 + lrow) * DIM + lch;
        cpasync16(sa, ga); cpasync16(sa + 16, ga + 8);
        uint32_t sb = sB_base + (uint32_t)(lrow * SROW + lch) * 2;
        const __nv_bfloat16* gb = Bg + (size_t)(n0 + lrow) * DIM + lch;
        cpasync16(sb, gb); cpasync16(sb + 16, gb + 8);
        asm volatile("cp.async.commit_group;");
    }

    const int lr = lane & 15;
    const int lc = (lane >> 4) << 3;

    for (int it = 0; it < DIM / 32; it++) {
        if (it + 1 < DIM / 32) {
            int st = (it + 1) & 1;
            int k0 = (it + 1) * 32;
            uint32_t sa = sA_base + st * stageBytes + (uint32_t)(lrow * SROW + lch) * 2;
            const __nv_bfloat16* ga = Ag + (size_t)(m0 + lrow) * DIM + k0 + lch;
            cpasync16(sa, ga); cpasync16(sa + 16, ga + 8);
            uint32_t sb = sB_base + st * stageBytes + (uint32_t)(lrow * SROW + lch) * 2;
            const __nv_bfloat16* gb = Bg + (size_t)(n0 + lrow) * DIM + k0 + lch;
            cpasync16(sb, gb); cpasync16(sb + 16, gb + 8);
            asm volatile("cp.async.commit_group;");
            asm volatile("cp.async.wait_group 1;");
        } else {
            asm volatile("cp.async.wait_group 0;");
        }
        __syncthreads();

        const int st = it & 1;
        const uint32_t aB = sA_base + st * stageBytes;
        const uint32_t bB = sB_base + st * stageBytes;

        #pragma unroll
        for (int kf = 0; kf < 2; kf++) {
            uint32_t a[4][4];
            #pragma unroll
            for (int mf = 0; mf < 4; mf++) {
                uint32_t addr = aB + (uint32_t)((wm * 64 + mf * 16 + lr) * SROW + kf * 16 + lc) * 2;
                ldsm4(a[mf][0], a[mf][1], a[mf][2], a[mf][3], addr);
            }
            uint32_t bq[2][4];
            #pragma unroll
            for (int nf2 = 0; nf2 < 2; nf2++) {
                uint32_t addr = bB + (uint32_t)((wn * 32 + nf2 * 16 + lr) * SROW + kf * 16 + lc) * 2;
                ldsm4(bq[nf2][0], bq[nf2][1], bq[nf2][2], bq[nf2][3], addr);
            }
            #pragma unroll
            for (int mf = 0; mf < 4; mf++)
                #pragma unroll
                for (int nf = 0; nf < 4; nf++) {
                    uint32_t b0 = bq[nf >> 1][nf & 1];
                    uint32_t b1 = bq[nf >> 1][(nf & 1) + 2];
                    mma16816(acc[mf][nf][0], acc[mf][nf][1], acc[mf][nf][2], acc[mf][nf][3],
                             a[mf][0], a[mf][1], a[mf][2], a[mf][3], b0, b1);
                }
        }
        __syncthreads();
    }

    #pragma unroll
    for (int mf = 0; mf < 4; mf++) {
        int row = m0 + wm * 64 + mf * 16 + (lane >> 2);
        #pragma unroll
        for (int nf = 0; nf < 4; nf++) {
            int col = n0 + wn * 32 + nf * 8 + (lane & 3) * 2;
            *(float2*)&Cb[(size_t)row * NPTS + col] =
                make_float2(acc[mf][nf][0], acc[mf][nf][1]);
            *(float2*)&Cb[(size_t)(row + 8) * NPTS + col] =
                make_float2(acc[mf][nf][2], acc[mf][nf][3]);
        }
    }
}

// =====================================================================
// Kernel 3: per row -- top-32 candidates on bf16-GEMM values, then
// EXACT fp32 rescore with the round-7-identical op sequence
// (sequential ascending-k fmaf, one thread per candidate), then exact
// top-16 with (value desc, idx asc). grid NROWS, block 128
// =====================================================================
__global__ __launch_bounds__(128) void select_rescore_kernel(float* __restrict__ outF) {
    const int row = blockIdx.x;
    const int b   = row >> 11;
    const int tid = threadIdx.x;
    const int lane = tid & 31, wid = tid >> 5;
    const float* wrow = g_w1 + (size_t)row * NPTS;

    __shared__ float fqs[DIM];
    __shared__ float swv[4];
    __shared__ int   swi[4];
    __shared__ int   cand[NCAND];
    __shared__ float rv[NCAND];
    __shared__ int   sWin;
    __shared__ int   sel[KNN];

    // each thread owns 16 contiguous bf16-gemm values in registers
    float v[16];
    {
        const float4* w4 = (const float4*)(wrow + tid * 16);
        float4 x0 = w4[0], x1 = w4[1], x2 = w4[2], x3 = w4[3];
        v[0]=x0.x; v[1]=x0.y; v[2]=x0.z; v[3]=x0.w;
        v[4]=x1.x; v[5]=x1.y; v[6]=x1.z; v[7]=x1.w;
        v[8]=x2.x; v[9]=x2.y; v[10]=x2.z; v[11]=x2.w;
        v[12]=x3.x; v[13]=x3.y; v[14]=x3.z; v[15]=x3.w;
    }
    // stage fq row (exact fp32 bits) for rescore
    {
        const float* fqr = g_fq + (size_t)row * DIM;
        #pragma unroll
        for (int j = 0; j < 4; j++) fqs[tid + j * 128] = fqr[tid + j * 128];
    }

    float lv = -INFINITY; int li = -1;
    #pragma unroll
    for (int j = 0; j < 16; j++)              // ascending, strict > -> lowest idx on tie
        if (v[j] > lv) { lv = v[j]; li = j; }
    const int gbase = tid * 16;

    for (int it = 0; it < NCAND; it++) {
        float bv = lv;
        int   bi = (li >= 0) ? (gbase + li) : NPTS;
        #pragma unroll
        for (int o = 16; o > 0; o >>= 1) {
            float ov = __shfl_xor_sync(0xffffffffu, bv, o);
            int   oi = __shfl_xor_sync(0xffffffffu, bi, o);
            if (ov > bv || (ov == bv && oi < bi)) { bv = ov; bi = oi; }
        }
        if (lane == 0) { swv[wid] = bv; swi[wid] = bi; }
        __syncthreads();
        if (tid == 0) {
            float fb = swv[0]; int fi = swi[0];
            #pragma unroll
            for (int w2 = 1; w2 < 4; w2++)
                if (swv[w2] > fb || (swv[w2] == fb && swi[w2] < fi)) { fb = swv[w2]; fi = swi[w2]; }
            cand[it] = fi; sWin = fi;
        }
        __syncthreads();
        int win = sWin;
        if ((win >> 4) == tid) {
            v[win & 15] = -INFINITY;
            lv = -INFINITY; li = -1;
            #pragma unroll
            for (int j = 0; j < 16; j++)
                if (v[j] > lv) { lv = v[j]; li = j; }
        }
    }
    __syncthreads();

    // EXACT rescore: thread c handles candidate c with the round-7 op
    // sequence: s_{k+1} = fmaf(fq[k], fp[k], s_k), k ascending from 0.
    const float* fpB = g_fp + (size_t)b * NPTS * DIM;
    if (tid < NCAND) {
        const float* fpr = fpB + (size_t)cand[tid] * DIM;
        float s = 0.f;
        #pragma unroll 8
        for (int k = 0; k < DIM; k++)
            s = fmaf(fqs[k], __ldg(&fpr[k]), s);
        rv[tid] = s;
    }
    __syncthreads();

    // exact top-16 among 32 (value desc, global idx asc), warp 0
    if (wid == 0) {
        float fv = rv[lane];
        int   fi = cand[lane];
        for (int it = 0; it < KNN; it++) {
            float bv = fv; int bi = fi;
            #pragma unroll
            for (int o = 16; o > 0; o >>= 1) {
                float ov = __shfl_xor_sync(0xffffffffu, bv, o);
                int   oi = __shfl_xor_sync(0xffffffffu, bi, o);
                if (ov > bv || (ov == bv && oi < bi)) { bv = ov; bi = oi; }
            }
            if (lane == 0) sel[it] = bi;
            if (fv == bv && fi == bi) fv = -INFINITY;   // remove winner (unique idx)
        }
    }
    __syncthreads();
    if (tid < KNN) {
        int s = sel[tid];
        g_topk[(size_t)row * KNN + tid] = s;
        outF[(size_t)3 * NROWS * 3 + (size_t)row * KNN + tid] = (float)s;
    }
}

// =====================================================================
// Kernel 4: gather(float4) + mean/max pool + refine linear + inv(R1,R2)
//           + masked residual. grid NROWS, block 128
// =====================================================================
__device__ __forceinline__ void inv3_apply(const float* __restrict__ M,
                                           const float* v, float* out) {
    float a = M[0], b = M[1], c = M[2];
    float d = M[3], e = M[4], f = M[5];
    float g = M[6], h = M[7], i = M[8];
    float det = a * (e * i - f * h) - b * (d * i - f * g) + c * (d * h - e * g);
    float idet = 1.0f / det;
    float i00 = (e*i - f*h)*idet, i01 = (c*h - b*i)*idet, i02 = (b*f - c*e)*idet;
    float i10 = (f*g - d*i)*idet, i11 = (a*i - c*g)*idet, i12 = (c*d - a*f)*idet;
    float i20 = (d*h - e*g)*idet, i21 = (b*g - a*h)*idet, i22 = (a*e - b*d)*idet;
    out[0] = i00*v[0] + i01*v[1] + i02*v[2];
    out[1] = i10*v[0] + i11*v[1] + i12*v[2];
    out[2] = i20*v[0] + i21*v[1] + i22*v[2];
}

__global__ __launch_bounds__(128) void finalize_kernel(
        const float* __restrict__ q,
        const float* __restrict__ ffp,
        const float* __restrict__ ffq,
        const float* __restrict__ R1,
        const float* __restrict__ R2,
        const int*   __restrict__ centroids,
        const float* __restrict__ W,
        const float* __restrict__ bias,
        float* __restrict__ outF) {
    const int pt  = blockIdx.x;
    const int b   = pt >> 11;
    const int tid = threadIdx.x;

    __shared__ int   sidx[KNN];
    __shared__ float s0[128], s1[128], s2[128];
    if (tid < KNN) sidx[tid] = g_topk[(size_t)pt * KNN + tid];
    __syncthreads();

    const float* fpB = ffp + (size_t)b * NPTS * DIM;
    const int d = tid * 4;

    float4 sum = make_float4(0.f, 0.f, 0.f, 0.f);
    float4 mx  = make_float4(-INFINITY, -INFINITY, -INFINITY, -INFINITY);
    #pragma unroll
    for (int k = 0; k < KNN; k++) {
        float4 fv = __ldg((const float4*)&fpB[(size_t)sidx[k] * DIM + d]);
        sum.x += fv.x; sum.y += fv.y; sum.z += fv.z; sum.w += fv.w;
        mx.x = fmaxf(mx.x, fv.x); mx.y = fmaxf(mx.y, fv.y);
        mx.z = fmaxf(mx.z, fv.z); mx.w = fmaxf(mx.w, fv.w);
    }
    const float inv16 = 1.0f / KNN;
    float4 avg = make_float4(sum.x * inv16, sum.y * inv16, sum.z * inv16, sum.w * inv16);
    float4 qv  = *(const float4*)&ffq[(size_t)pt * DIM + d];

    float p[3];
    #pragma unroll
    for (int o = 0; o < 3; o++) {
        float4 w0 = __ldg((const float4*)&W[o * 1536 + d]);
        float4 w1 = __ldg((const float4*)&W[o * 1536 + 512 + d]);
        float4 w2 = __ldg((const float4*)&W[o * 1536 + 1024 + d]);
        p[o] = qv.x*w0.x + qv.y*w0.y + qv.z*w0.z + qv.w*w0.w
             + avg.x*w1.x + avg.y*w1.y + avg.z*w1.z + avg.w*w1.w
             + mx.x*w2.x + mx.y*w2.y + mx.z*w2.z + mx.w*w2.w;
    }
    s0[tid] = p[0]; s1[tid] = p[1]; s2[tid] = p[2];
    __syncthreads();
    #pragma unroll
    for (int s = 64; s > 0; s >>= 1) {
        if (tid < s) { s0[tid] += s0[tid+s]; s1[tid] += s1[tid+s]; s2[tid] += s2[tid+s]; }
        __syncthreads();
    }
    if (tid == 0) {
        float vv[3] = { s0[0] + bias[0], s1[0] + bias[1], s2[0] + bias[2] };
        float t[3], r[3];
        inv3_apply(R1 + (size_t)pt * 9, vv, t);
        inv3_apply(R2 + (size_t)pt * 9, t, r);
        float mask = (centroids[pt] >= NPTS) ? 1.0f : 0.0f;

        size_t base = (size_t)pt * 3;
        float q0 = q[base], q1 = q[base+1], q2 = q[base+2];
        outF[base] = q0; outF[base+1] = q1; outF[base+2] = q2;
        float o0 = q0 + r[0]*mask, o1 = q1 + r[1]*mask, o2 = q2 + r[2]*mask;
        size_t off = (size_t)NROWS * 3;
        outF[off + base] = o0;     outF[off + base+1] = o1;     outF[off + base+2] = o2;
        outF[2*off + base] = o0;   outF[2*off + base+1] = o1;   outF[2*off + base+2] = o2;
    }
}

// =====================================================================
extern "C" void kernel_launch(void* const* d_in, const int* in_sizes, int n_in,
                              void* d_out, int out_size) {
    const float* q         = (const float*)d_in[1];
    const float* ffp       = (const float*)d_in[2];
    const float* ffq       = (const float*)d_in[3];
    const float* R1        = (const float*)d_in[4];
    const float* R2        = (const float*)d_in[5];
    const int*   centroids = (const int*)  d_in[6];
    const float* W         = (const float*)d_in[7];
    const float* bias      = (const float*)d_in[8];
    float* outF = (float*)d_out;

    dim3 gN(NROWS, 2);
    normalize_kernel<<<gN, 256>>>(ffq, ffp);
    cast_bf16_kernel<<<gN, 256>>>();

    dim3 gG(NPTS / BN, NPTS / BM, BATCH);
    gemm_bf16_kernel<<<gG, 256>>>();

    select_rescore_kernel<<<NROWS, 128>>>(outF);

    finalize_kernel<<<NROWS, 128>>>(q, ffp, ffq, R1, R2, centroids, W, bias, outF);
}

// round 15
// speedup vs baseline: 3.5555x; 2.1381x over previous
#include <cuda_runtime.h>
#include <cuda_bf16.h>
#include <math.h>
#include <stdint.h>

#define BATCH 8
#define NPTS  2048
#define DIM   512
#define KNN   16
#define NROWS (BATCH*NPTS)
#define NCAND 32

// ---------- scratch (static device globals; no runtime allocation) ----------
__device__ __align__(16) float         g_fq [(size_t)NROWS*DIM];   // normalized ffq (fp32)
__device__ __align__(16) float         g_fp [(size_t)NROWS*DIM];   // normalized ffp (fp32)
// bf16 copies in GEMM-ready tiled+swizzled layout:
// tile (b, rb, kb) = 128 rows x 64 cols bf16 = 16KB contiguous at
//   ((b*16 + rb)*8 + kb) * 16384 bytes
// within tile: element (r, k): byte = r*128 + (((k>>3) ^ (r&7))<<4) + (k&7)*2
__device__ __align__(16) __nv_bfloat16 g_fqb[(size_t)NROWS*DIM];
__device__ __align__(16) __nv_bfloat16 g_fpb[(size_t)NROWS*DIM];
__device__ __align__(16) float         g_w1 [(size_t)NROWS*NPTS];  // bf16-mma similarity
__device__ int                         g_topk[(size_t)NROWS*KNN];

// =====================================================================
// Kernel 1: row L2-normalize (verbatim round-7 math; g_fq/g_fp bits
// identical to the passing kernel). grid (NROWS, 2), block 256
// =====================================================================
__global__ void normalize_kernel(const float* __restrict__ ffq,
                                 const float* __restrict__ ffp) {
    int row = blockIdx.x;
    const float* src = (blockIdx.y == 0) ? ffq : ffp;
    float*       dst = (blockIdx.y == 0) ? g_fq : g_fp;
    const float* r = src + (size_t)row * DIM;
    int tid = threadIdx.x;

    float v0 = r[tid], v1 = r[tid + 256];
    __shared__ float red[256];
    red[tid] = v0 * v0 + v1 * v1;
    __syncthreads();
    #pragma unroll
    for (int s = 128; s > 0; s >>= 1) {
        if (tid < s) red[tid] += red[tid + s];
        __syncthreads();
    }
    float inv = 1.0f / (sqrtf(red[0]) + 1e-8f);
    float* d = dst + (size_t)row * DIM;
    d[tid]       = v0 * inv;
    d[tid + 256] = v1 * inv;
}

// =====================================================================
// Kernel 1b: fp32 -> bf16 cast + tiled/swizzled layout transform.
// grid (NROWS/4, 2), block 256: 4 rows/block, one 16B chunk per thread.
// =====================================================================
__global__ void cast_swizzle_kernel() {
    const int row = blockIdx.x * 4 + (threadIdx.x >> 6);
    const int c   = threadIdx.x & 63;          // 16B chunk index within row (0..63)
    const float*   src = (blockIdx.y == 0) ? g_fq : g_fp;
    __nv_bfloat16* dst = (blockIdx.y == 0) ? g_fqb : g_fpb;

    const int b  = row >> 11;
    const int n  = row & 2047;
    const int rb = n >> 7;
    const int r  = n & 127;
    const int kb = c >> 3;
    const int ch = c & 7;

    const float* s = src + (size_t)row * DIM + c * 8;
    float4 f0 = *(const float4*)(s);
    float4 f1 = *(const float4*)(s + 4);

    __nv_bfloat162 h[4];
    h[0] = __nv_bfloat162(__float2bfloat16(f0.x), __float2bfloat16(f0.y));
    h[1] = __nv_bfloat162(__float2bfloat16(f0.z), __float2bfloat16(f0.w));
    h[2] = __nv_bfloat162(__float2bfloat16(f1.x), __float2bfloat16(f1.y));
    h[3] = __nv_bfloat162(__float2bfloat16(f1.z), __float2bfloat16(f1.w));

    size_t tile = ((size_t)(b * 16 + rb) * 8 + kb) << 14;   // bytes
    char* d = (char*)dst + tile + r * 128 + ((ch ^ (r & 7)) << 4);
    *(uint4*)d = *(uint4*)h;
}

// =====================================================================
// Kernel 2: bf16 mma.sync GEMM  w1[b,q,p] = fq[b,q,:].fp[b,p,:]
// CTA tile 128x128, BK=64, 8 warps (2x4), warp tile 64x32.
// Loads: one 16KB cp.async.bulk per matrix per stage (pre-swizzled
// tiles), 2-stage mbarrier pipeline, one-iteration lookahead.
// grid (16, 16, 8), block 256, dynamic smem 66560B.
// =====================================================================
#define SM_MBAR   0          // two 8B mbarriers at 0, 8
#define SM_TILES  1024       // 4 x 16KB: [stage][A|B]
#define TILE_BYTES 16384
#define SMEM_GEMM_TOTAL (1024 + 4*TILE_BYTES)
#define NIT 8                // DIM / 64

__device__ __forceinline__ void ldsm4(uint32_t& r0, uint32_t& r1,
                                      uint32_t& r2, uint32_t& r3, uint32_t addr) {
    asm volatile("ldmatrix.sync.aligned.m8n8.x4.shared.b16 {%0,%1,%2,%3}, [%4];"
                 : "=r"(r0), "=r"(r1), "=r"(r2), "=r"(r3) : "r"(addr));
}
__device__ __forceinline__ void mma16816(float& c0, float& c1, float& c2, float& c3,
                                         uint32_t a0, uint32_t a1, uint32_t a2, uint32_t a3,
                                         uint32_t b0, uint32_t b1) {
    asm volatile("mma.sync.aligned.m16n8k16.row.col.f32.bf16.bf16.f32 "
                 "{%0,%1,%2,%3}, {%4,%5,%6,%7}, {%8,%9}, {%0,%1,%2,%3};"
                 : "+f"(c0), "+f"(c1), "+f"(c2), "+f"(c3)
                 : "r"(a0), "r"(a1), "r"(a2), "r"(a3), "r"(b0), "r"(b1));
}
__device__ __forceinline__ void bulk_ld(uint32_t dst_smem, const void* gsrc,
                                        uint32_t bytes, uint32_t mbar) {
    uint64_t gaddr;
    asm volatile("cvta.to.global.u64 %0, %1;" : "=l"(gaddr) : "l"(gsrc));
    asm volatile("cp.async.bulk.shared::cluster.global.mbarrier::complete_tx::bytes "
                 "[%0], [%1], %2, [%3];"
                 :: "r"(dst_smem), "l"(gaddr), "r"(bytes), "r"(mbar) : "memory");
}
__device__ __forceinline__ void mbar_expect_tx(uint32_t mbar, uint32_t bytes) {
    asm volatile("mbarrier.arrive.expect_tx.shared.b64 _, [%0], %1;"
                 :: "r"(mbar), "r"(bytes) : "memory");
}
__device__ __forceinline__ void mbar_wait_parity(uint32_t mbar, uint32_t parity) {
    asm volatile(
        "{\n\t.reg .pred P1;\n\t"
        "WAIT_LOOP_%=:\n\t"
        "mbarrier.try_wait.parity.acquire.cta.shared::cta.b64 P1, [%0], %1, 0x989680;\n\t"
        "@P1 bra.uni WAIT_DONE_%=;\n\t"
        "bra.uni WAIT_LOOP_%=;\n\t"
        "WAIT_DONE_%=:\n\t}"
        :: "r"(mbar), "r"(parity) : "memory");
}

__global__ __launch_bounds__(256, 2) void gemm_bf16_kernel() {
    extern __shared__ __align__(1024) char smem[];
    const int tid = threadIdx.x;
    const int lane = tid & 31, wid = tid >> 5;
    const int wm = wid >> 2, wn = wid & 3;     // warp grid 2(m) x 4(n)
    const int b  = blockIdx.z;
    const int mb = blockIdx.y;                  // 128-row block of fq
    const int nb = blockIdx.x;                  // 128-row block of fp
    float* Cb = g_w1 + (size_t)b * NPTS * NPTS;

    const uint32_t sbase = (uint32_t)__cvta_generic_to_shared(smem);
    const uint32_t mbar0 = sbase + SM_MBAR;
    const char* Abase = (const char*)g_fqb + (((size_t)(b * 16 + mb) * 8) << 14);
    const char* Bbase = (const char*)g_fpb + (((size_t)(b * 16 + nb) * 8) << 14);

    if (tid == 0) {
        asm volatile("mbarrier.init.shared.b64 [%0], %1;" :: "r"(mbar0), "r"(1u) : "memory");
        asm volatile("mbarrier.init.shared.b64 [%0], %1;" :: "r"(mbar0 + 8), "r"(1u) : "memory");
    }
    __syncthreads();

    // prologue: arm + load stage 0 (k-block 0)
    if (tid == 0) {
        mbar_expect_tx(mbar0, 2 * TILE_BYTES);
        bulk_ld(sbase + SM_TILES,              Abase, TILE_BYTES, mbar0);
        bulk_ld(sbase + SM_TILES + TILE_BYTES, Bbase, TILE_BYTES, mbar0);
    }

    float acc[4][4][4];
    #pragma unroll
    for (int i = 0; i < 4; i++)
        #pragma unroll
        for (int j = 0; j < 4; j++)
            #pragma unroll
            for (int v = 0; v < 4; v++) acc[i][j][v] = 0.f;

    const int lr  = lane & 15;       // fragment row within 16
    const int lhi = lane >> 4;       // which 16B chunk half

    for (int it = 0; it < NIT; it++) {
        const int st = it & 1;
        // lookahead: arm + load next stage (its previous readers finished
        // at the __syncthreads ending iteration it-1)
        if (tid == 0 && it + 1 < NIT) {
            const int ns = (it + 1) & 1;
            const uint32_t nm = mbar0 + ns * 8;
            mbar_expect_tx(nm, 2 * TILE_BYTES);
            bulk_ld(sbase + SM_TILES + ns * 2 * TILE_BYTES,
                    Abase + (size_t)(it + 1) * TILE_BYTES, TILE_BYTES, nm);
            bulk_ld(sbase + SM_TILES + ns * 2 * TILE_BYTES + TILE_BYTES,
                    Bbase + (size_t)(it + 1) * TILE_BYTES, TILE_BYTES, nm);
        }
        mbar_wait_parity(mbar0 + st * 8, (uint32_t)((it >> 1) & 1));

        const uint32_t aT = sbase + SM_TILES + st * 2 * TILE_BYTES;
        const uint32_t bT = aT + TILE_BYTES;

        #pragma unroll
        for (int kf = 0; kf < 4; kf++) {
            const int ch = 2 * kf + lhi;       // 16B chunk index 0..7
            uint32_t a[4][4];
            #pragma unroll
            for (int mf = 0; mf < 4; mf++) {
                int r = wm * 64 + mf * 16 + lr;
                uint32_t addr = aT + (uint32_t)(r * 128 + ((ch ^ (r & 7)) << 4));
                ldsm4(a[mf][0], a[mf][1], a[mf][2], a[mf][3], addr);
            }
            uint32_t bq[2][4];
            #pragma unroll
            for (int nf2 = 0; nf2 < 2; nf2++) {
                int r = wn * 32 + nf2 * 16 + lr;
                uint32_t addr = bT + (uint32_t)(r * 128 + ((ch ^ (r & 7)) << 4));
                ldsm4(bq[nf2][0], bq[nf2][1], bq[nf2][2], bq[nf2][3], addr);
            }
            #pragma unroll
            for (int mf = 0; mf < 4; mf++)
                #pragma unroll
                for (int nf = 0; nf < 4; nf++) {
                    uint32_t b0 = bq[nf >> 1][nf & 1];
                    uint32_t b1 = bq[nf >> 1][(nf & 1) + 2];
                    mma16816(acc[mf][nf][0], acc[mf][nf][1], acc[mf][nf][2], acc[mf][nf][3],
                             a[mf][0], a[mf][1], a[mf][2], a[mf][3], b0, b1);
                }
        }
        __syncthreads();   // all readers done with stage st before it is re-armed
    }

    // epilogue (round-11 proven mapping)
    #pragma unroll
    for (int mf = 0; mf < 4; mf++) {
        int row = mb * 128 + wm * 64 + mf * 16 + (lane >> 2);
        #pragma unroll
        for (int nf = 0; nf < 4; nf++) {
            int col = nb * 128 + wn * 32 + nf * 8 + (lane & 3) * 2;
            *(float2*)&Cb[(size_t)row * NPTS + col] =
                make_float2(acc[mf][nf][0], acc[mf][nf][1]);
            *(float2*)&Cb[(size_t)(row + 8) * NPTS + col] =
                make_float2(acc[mf][nf][2], acc[mf][nf][3]);
        }
    }
}

// =====================================================================
// Kernel 3: per row -- top-32 candidates on bf16-GEMM values, then
// EXACT fp32 rescore (round-7-identical ascending fmaf sequence, rows
// staged in smem in 128-float chunks), then exact top-16
// (value desc, idx asc). grid NROWS, block 128
// =====================================================================
#define SCR_STRIDE 133   // 133 mod 32 = 5 -> conflict-free strided reads

__global__ __launch_bounds__(128) void select_rescore_kernel(float* __restrict__ outF) {
    const int row = blockIdx.x;
    const int b   = row >> 11;
    const int tid = threadIdx.x;
    const int lane = tid & 31, wid = tid >> 5;
    const float* wrow = g_w1 + (size_t)row * NPTS;

    __shared__ float fqs[DIM];
    __shared__ float scr[NCAND * SCR_STRIDE];
    __shared__ float swv[4];
    __shared__ int   swi[4];
    __shared__ int   cand[NCAND];
    __shared__ float rv[NCAND];
    __shared__ int   sWin;
    __shared__ int   sel[KNN];

    float v[16];
    {
        const float4* w4 = (const float4*)(wrow + tid * 16);
        float4 x0 = w4[0], x1 = w4[1], x2 = w4[2], x3 = w4[3];
        v[0]=x0.x; v[1]=x0.y; v[2]=x0.z; v[3]=x0.w;
        v[4]=x1.x; v[5]=x1.y; v[6]=x1.z; v[7]=x1.w;
        v[8]=x2.x; v[9]=x2.y; v[10]=x2.z; v[11]=x2.w;
        v[12]=x3.x; v[13]=x3.y; v[14]=x3.z; v[15]=x3.w;
    }
    {
        const float* fqr = g_fq + (size_t)row * DIM;
        #pragma unroll
        for (int j = 0; j < 4; j++) fqs[tid + j * 128] = fqr[tid + j * 128];
    }

    float lv = -INFINITY; int li = -1;
    #pragma unroll
    for (int j = 0; j < 16; j++)              // ascending, strict > -> lowest idx on tie
        if (v[j] > lv) { lv = v[j]; li = j; }
    const int gbase = tid * 16;

    for (int it = 0; it < NCAND; it++) {
        float bv = lv;
        int   bi = (li >= 0) ? (gbase + li) : NPTS;
        #pragma unroll
        for (int o = 16; o > 0; o >>= 1) {
            float ov = __shfl_xor_sync(0xffffffffu, bv, o);
            int   oi = __shfl_xor_sync(0xffffffffu, bi, o);
            if (ov > bv || (ov == bv && oi < bi)) { bv = ov; bi = oi; }
        }
        if (lane == 0) { swv[wid] = bv; swi[wid] = bi; }
        __syncthreads();
        if (tid == 0) {
            float fb = swv[0]; int fi = swi[0];
            #pragma unroll
            for (int w2 = 1; w2 < 4; w2++)
                if (swv[w2] > fb || (swv[w2] == fb && swi[w2] < fi)) { fb = swv[w2]; fi = swi[w2]; }
            cand[it] = fi; sWin = fi;
        }
        __syncthreads();
        int win = sWin;
        if ((win >> 4) == tid) {
            v[win & 15] = -INFINITY;
            lv = -INFINITY; li = -1;
            #pragma unroll
            for (int j = 0; j < 16; j++)
                if (v[j] > lv) { lv = v[j]; li = j; }
        }
    }
    __syncthreads();

    // EXACT rescore (round-7 op sequence): candidate rows staged
    // cooperatively; thread c<32: s = fmaf(fq[k], fp[k], s), k ascending.
    const float* fpB = g_fp + (size_t)b * NPTS * DIM;
    float s = 0.f;
    #pragma unroll
    for (int c0 = 0; c0 < DIM; c0 += 128) {
        __syncthreads();
        #pragma unroll
        for (int j = 0; j < 8; j++) {
            int g  = j * 128 + tid;
            int cc = g >> 5, k4 = g & 31;
            float4 fv = __ldg((const float4*)(fpB + (size_t)cand[cc] * DIM + c0 + k4 * 4));
            float* dst = &scr[cc * SCR_STRIDE + k4 * 4];
            dst[0] = fv.x; dst[1] = fv.y; dst[2] = fv.z; dst[3] = fv.w;
        }
        __syncthreads();
        if (tid < NCAND) {
            const float* sr = &scr[tid * SCR_STRIDE];
            #pragma unroll 8
            for (int kk = 0; kk < 128; kk++)
                s = fmaf(fqs[c0 + kk], sr[kk], s);
        }
    }
    if (tid < NCAND) rv[tid] = s;
    __syncthreads();

    if (wid == 0) {
        float fv = rv[lane];
        int   fi = cand[lane];
        for (int it = 0; it < KNN; it++) {
            float bv = fv; int bi = fi;
            #pragma unroll
            for (int o = 16; o > 0; o >>= 1) {
                float ov = __shfl_xor_sync(0xffffffffu, bv, o);
                int   oi = __shfl_xor_sync(0xffffffffu, bi, o);
                if (ov > bv || (ov == bv && oi < bi)) { bv = ov; bi = oi; }
            }
            if (lane == 0) sel[it] = bi;
            if (fv == bv && fi == bi) fv = -INFINITY;
        }
    }
    __syncthreads();
    if (tid < KNN) {
        int sidx = sel[tid];
        g_topk[(size_t)row * KNN + tid] = sidx;
        outF[(size_t)3 * NROWS * 3 + (size_t)row * KNN + tid] = (float)sidx;
    }
}

// =====================================================================
// Kernel 4: gather(float4) + mean/max pool + refine linear + inv(R1,R2)
//           + masked residual. grid NROWS, block 128
// =====================================================================
__device__ __forceinline__ void inv3_apply(const float* __restrict__ M,
                                           const float* v, float* out) {
    float a = M[0], b = M[1], c = M[2];
    float d = M[3], e = M[4], f = M[5];
    float g = M[6], h = M[7], i = M[8];
    float det = a * (e * i - f * h) - b * (d * i - f * g) + c * (d * h - e * g);
    float idet = 1.0f / det;
    float i00 = (e*i - f*h)*idet, i01 = (c*h - b*i)*idet, i02 = (b*f - c*e)*idet;
    float i10 = (f*g - d*i)*idet, i11 = (a*i - c*g)*idet, i12 = (c*d - a*f)*idet;
    float i20 = (d*h - e*g)*idet, i21 = (b*g - a*h)*idet, i22 = (a*e - b*d)*idet;
    out[0] = i00*v[0] + i01*v[1] + i02*v[2];
    out[1] = i10*v[0] + i11*v[1] + i12*v[2];
    out[2] = i20*v[0] + i21*v[1] + i22*v[2];
}

__global__ __launch_bounds__(128) void finalize_kernel(
        const float* __restrict__ q,
        const float* __restrict__ ffp,
        const float* __restrict__ ffq,
        const float* __restrict__ R1,
        const float* __restrict__ R2,
        const int*   __restrict__ centroids,
        const float* __restrict__ W,
        const float* __restrict__ bias,
        float* __restrict__ outF) {
    const int pt  = blockIdx.x;
    const int b   = pt >> 11;
    const int tid = threadIdx.x;

    __shared__ int   sidx[KNN];
    __shared__ float s0[128], s1[128], s2[128];
    if (tid < KNN) sidx[tid] = g_topk[(size_t)pt * KNN + tid];
    __syncthreads();

    const float* fpB = ffp + (size_t)b * NPTS * DIM;
    const int d = tid * 4;

    float4 sum = make_float4(0.f, 0.f, 0.f, 0.f);
    float4 mx  = make_float4(-INFINITY, -INFINITY, -INFINITY, -INFINITY);
    #pragma unroll
    for (int k = 0; k < KNN; k++) {
        float4 fv = __ldg((const float4*)&fpB[(size_t)sidx[k] * DIM + d]);
        sum.x += fv.x; sum.y += fv.y; sum.z += fv.z; sum.w += fv.w;
        mx.x = fmaxf(mx.x, fv.x); mx.y = fmaxf(mx.y, fv.y);
        mx.z = fmaxf(mx.z, fv.z); mx.w = fmaxf(mx.w, fv.w);
    }
    const float inv16 = 1.0f / KNN;
    float4 avg = make_float4(sum.x * inv16, sum.y * inv16, sum.z * inv16, sum.w * inv16);
    float4 qv  = *(const float4*)&ffq[(size_t)pt * DIM + d];

    float p[3];
    #pragma unroll
    for (int o = 0; o < 3; o++) {
        float4 w0 = __ldg((const float4*)&W[o * 1536 + d]);
        float4 w1 = __ldg((const float4*)&W[o * 1536 + 512 + d]);
        float4 w2 = __ldg((const float4*)&W[o * 1536 + 1024 + d]);
        p[o] = qv.x*w0.x + qv.y*w0.y + qv.z*w0.z + qv.w*w0.w
             + avg.x*w1.x + avg.y*w1.y + avg.z*w1.z + avg.w*w1.w
             + mx.x*w2.x + mx.y*w2.y + mx.z*w2.z + mx.w*w2.w;
    }
    s0[tid] = p[0]; s1[tid] = p[1]; s2[tid] = p[2];
    __syncthreads();
    #pragma unroll
    for (int s = 64; s > 0; s >>= 1) {
        if (tid < s) { s0[tid] += s0[tid+s]; s1[tid] += s1[tid+s]; s2[tid] += s2[tid+s]; }
        __syncthreads();
    }
    if (tid == 0) {
        float vv[3] = { s0[0] + bias[0], s1[0] + bias[1], s2[0] + bias[2] };
        float t[3], r[3];
        inv3_apply(R1 + (size_t)pt * 9, vv, t);
        inv3_apply(R2 + (size_t)pt * 9, t, r);
        float mask = (centroids[pt] >= NPTS) ? 1.0f : 0.0f;

        size_t base = (size_t)pt * 3;
        float q0 = q[base], q1 = q[base+1], q2 = q[base+2];
        outF[base] = q0; outF[base+1] = q1; outF[base+2] = q2;
        float o0 = q0 + r[0]*mask, o1 = q1 + r[1]*mask, o2 = q2 + r[2]*mask;
        size_t off = (size_t)NROWS * 3;
        outF[off + base] = o0;     outF[off + base+1] = o1;     outF[off + base+2] = o2;
        outF[2*off + base] = o0;   outF[2*off + base+1] = o1;   outF[2*off + base+2] = o2;
    }
}

// =====================================================================
extern "C" void kernel_launch(void* const* d_in, const int* in_sizes, int n_in,
                              void* d_out, int out_size) {
    const float* q         = (const float*)d_in[1];
    const float* ffp       = (const float*)d_in[2];
    const float* ffq       = (const float*)d_in[3];
    const float* R1        = (const float*)d_in[4];
    const float* R2        = (const float*)d_in[5];
    const int*   centroids = (const int*)  d_in[6];
    const float* W         = (const float*)d_in[7];
    const float* bias      = (const float*)d_in[8];
    float* outF = (float*)d_out;

    // idempotent; not a stream op, safe under capture, no static guards
    cudaFuncSetAttribute(gemm_bf16_kernel,
                         cudaFuncAttributeMaxDynamicSharedMemorySize,
                         SMEM_GEMM_TOTAL);

    dim3 gN(NROWS, 2);
    normalize_kernel<<<gN, 256>>>(ffq, ffp);

    dim3 gC(NROWS / 4, 2);
    cast_swizzle_kernel<<<gC, 256>>>();

    dim3 gG(NPTS / 128, NPTS / 128, BATCH);
    gemm_bf16_kernel<<<gG, 256, SMEM_GEMM_TOTAL>>>();

    select_rescore_kernel<<<NROWS, 128>>>(outF);

    finalize_kernel<<<NROWS, 128>>>(q, ffp, ffq, R1, R2, centroids, W, bias, outF);
}